// round 13
// baseline (speedup 1.0000x reference)
#include <cuda_runtime.h>
#include <cuda_bf16.h>
#include <math.h>
#include <stdint.h>

#define B_  16
#define L_  1024
#define C_  128
#define H_  512
#define LC_ (L_*C_)      // 131072
#define M_  (B_*L_)      // 16384

// ---------------- device scratch ----------------
__device__ float g_h  [M_*H_];        // 32 MB hidden activations (fp32)
__device__ float g_eps[M_*C_];
__device__ float g_za [M_*C_];
__device__ float g_zb [M_*C_];
__device__ float g_ent[LC_];
__device__ float g_p1[(L_/2)*(C_/2)];   // 32768
__device__ float g_p2[(L_/4)*(C_/4)];   // 8192
__device__ float g_p3[(L_/8)*(C_/8)];   // 2048
__device__ float g_part[1024];          // 128 used per half
__device__ float g_T[4];
__device__ float g_stats[2];
__device__ unsigned g_hist[4 * 65536];  // zero-invariant across replays
__device__ unsigned g_pref[4];
__device__ unsigned g_krem[4];
// weight splits (3-term), transposed [N,K] row-major (K contiguous)
__device__ __nv_bfloat16 g_b1t0[H_*C_], g_b1t1[H_*C_], g_b1t2[H_*C_]; // [512,128]
__device__ __nv_bfloat16 g_b2t0[C_*H_], g_b2t1[C_*H_], g_b2t2[C_*H_]; // [128,512]

__constant__ int c_K[4] = { 26214, 6553, 1638, 409 };   // int(0.2 * pooled.size)

// ---------------- helpers ----------------
__device__ __forceinline__ uint32_t smem_u32(const void* p) {
    uint32_t a;
    asm("{ .reg .u64 t; cvta.to.shared.u64 t, %1; cvt.u32.u64 %0, t; }" : "=r"(a) : "l"(p));
    return a;
}
__device__ __forceinline__ void cp_async16(uint32_t s, const void* g) {
    asm volatile("cp.async.cg.shared.global [%0], [%1], 16;" :: "r"(s), "l"(g) : "memory");
}
#define STS64v(addr, r0, r1) \
    asm volatile("st.shared.v2.b32 [%0], {%1,%2};" :: "r"(addr), "r"(r0), "r"(r1) : "memory")
__device__ __forceinline__ void ldsm_x4(uint32_t* r, uint32_t addr) {
    asm volatile("ldmatrix.sync.aligned.m8n8.x4.shared.b16 {%0,%1,%2,%3}, [%4];"
                 : "=r"(r[0]), "=r"(r[1]), "=r"(r[2]), "=r"(r[3]) : "r"(addr));
}
__device__ __forceinline__ void mma16816(float* d, const uint32_t* a, const uint32_t* b) {
    asm volatile(
        "mma.sync.aligned.m16n8k16.row.col.f32.bf16.bf16.f32 "
        "{%0,%1,%2,%3}, {%4,%5,%6,%7}, {%8,%9}, {%0,%1,%2,%3};"
        : "+f"(d[0]), "+f"(d[1]), "+f"(d[2]), "+f"(d[3])
        : "r"(a[0]), "r"(a[1]), "r"(a[2]), "r"(a[3]), "r"(b[0]), "r"(b[1]));
}
// gelu(x) = x * sigmoid(2u); exactly 2 MUFU, no branch. (validated R10)
__device__ __forceinline__ float gelu_f(float x) {
    float x2 = x * x;
    float u  = 0.7978845608028654f * x + 0.035677408136300125f * x * x2;
    float e, r;
    asm("ex2.approx.f32 %0, %1;" : "=f"(e) : "f"(-2.8853900817779268f * u));
    asm("rcp.approx.f32 %0, %1;" : "=f"(r) : "f"(1.0f + e));
    return x * r;
}
__device__ __forceinline__ void split3(float x, unsigned short& h0, unsigned short& h1, unsigned short& h2) {
    __nv_bfloat16 b0 = __float2bfloat16_rn(x);
    float r1 = x - __bfloat162float(b0);
    __nv_bfloat16 b1 = __float2bfloat16_rn(r1);
    float r2 = r1 - __bfloat162float(b1);
    __nv_bfloat16 b2 = __float2bfloat16_rn(r2);
    h0 = __bfloat16_as_ushort(b0);
    h1 = __bfloat16_as_ushort(b1);
    h2 = __bfloat16_as_ushort(b2);
}

// ---------------- diagnostic no-op (shifts ncu onto gemm1) --------------
__global__ void noop_k() {}

// ---------------- weight prep: transpose + 3-way split ------------------
__global__ __launch_bounds__(256) void prep_k(const float* __restrict__ W1, const float* __restrict__ W2)
{
    int t = blockIdx.x * 256 + threadIdx.x;   // 131072 total
    float x; int idx;
    __nv_bfloat16 *d0, *d1, *d2;
    if (t < H_ * C_) {                        // B1t [512,128] from W1[128,512]
        idx = t; int n = idx >> 7, k = idx & 127;
        x = W1[k * H_ + n];
        d0 = g_b1t0; d1 = g_b1t1; d2 = g_b1t2;
    } else {                                  // B2t [128,512] from W2[512,128]
        idx = t - H_ * C_; int n = idx >> 9, k = idx & 511;
        x = W2[k * C_ + n];
        d0 = g_b2t0; d1 = g_b2t1; d2 = g_b2t2;
    }
    unsigned short h0, h1, h2;
    split3(x, h0, h1, h2);
    d0[idx] = __ushort_as_bfloat16(h0);
    d1[idx] = __ushort_as_bfloat16(h1);
    d2[idx] = __ushort_as_bfloat16(h2);
}

static constexpr int TERMB = 10240;   // 128 rows x 80B (64B data + 16B pad)

// ================= GEMM1: one-wave, A-resident ==========================
static constexpr int A1BYTES = 12 * TERMB;
static constexpr int SMEMB1  = A1BYTES + 6 * TERMB;  // 184320

__global__ __launch_bounds__(256, 1)
void gemm1_k(const float* __restrict__ A,
             const __nv_bfloat16* __restrict__ Bt0, const __nv_bfloat16* __restrict__ Bt1,
             const __nv_bfloat16* __restrict__ Bt2,
             const float* __restrict__ bias, const float* __restrict__ tw, float t_feat,
             float* __restrict__ out)
{
    extern __shared__ char smem[];
    const uint32_t sb = smem_u32(smem);
    const int tid = threadIdx.x, lane = tid & 31, wid = tid >> 5;
    const int m0 = blockIdx.x * 128;
    const int wm = (wid >> 2) * 64, wn = (wid & 3) * 32;

    auto cpB = [&](int n, int kt, int buf) {
        uint32_t base = sb + A1BYTES + buf * (3 * TERMB);
#pragma unroll
        for (int i = 0; i < 6; i++) {
            int rem = (i & 1) * 256 + tid;
            int row = rem >> 2, ch = rem & 3;
            const __nv_bfloat16* src = (i < 2) ? Bt0 : ((i < 4) ? Bt1 : Bt2);
            cp_async16(base + (i >> 1) * TERMB + row * 80 + ch * 16,
                       src + (size_t)(n * 128 + row) * C_ + kt * 32 + ch * 8);
        }
        asm volatile("cp.async.commit_group;" ::: "memory");
    };

    cpB(0, 0, 0);

#pragma unroll
    for (int c = 0; c < 4; c++) {
        float4 aR[4];
#pragma unroll
        for (int i = 0; i < 4; i++) {
            int f = tid + i * 256;
            aR[i] = *(const float4*)(A + (size_t)(m0 + (f >> 3)) * C_ + c * 32 + (f & 7) * 4);
        }
#pragma unroll
        for (int i = 0; i < 4; i++) {
            int f = tid + i * 256;
            float x[4] = { aR[i].x, aR[i].y, aR[i].z, aR[i].w };
            unsigned short s0[4], s1[4], s2[4];
#pragma unroll
            for (int j = 0; j < 4; j++) split3(x[j], s0[j], s1[j], s2[j]);
            uint32_t addr = sb + c * TERMB + (f >> 3) * 80 + (f & 7) * 8;
            STS64v(addr,                 (uint32_t)s0[0] | ((uint32_t)s0[1] << 16),
                                         (uint32_t)s0[2] | ((uint32_t)s0[3] << 16));
            STS64v(addr + 4 * TERMB,     (uint32_t)s1[0] | ((uint32_t)s1[1] << 16),
                                         (uint32_t)s1[2] | ((uint32_t)s1[3] << 16));
            STS64v(addr + 8 * TERMB,     (uint32_t)s2[0] | ((uint32_t)s2[1] << 16),
                                         (uint32_t)s2[2] | ((uint32_t)s2[3] << 16));
        }
    }

    const int PA[6] = { 0, 0, 1, 1, 0, 2 };
    const int PB[6] = { 0, 1, 0, 1, 2, 0 };
    int buf = 0;

#pragma unroll 1
    for (int n = 0; n < 4; n++) {
        float acc[4][4][4];
#pragma unroll
        for (int a = 0; a < 4; a++)
#pragma unroll
            for (int b = 0; b < 4; b++)
#pragma unroll
                for (int c = 0; c < 4; c++) acc[a][b][c] = 0.0f;

#pragma unroll 1
        for (int kt = 0; kt < 4; kt++) {
            int idx = n * 4 + kt;
            if (idx + 1 < 16) {
                int nn = (idx + 1) >> 2, nk = (idx + 1) & 3;
                cpB(nn, nk, buf ^ 1);
                asm volatile("cp.async.wait_group 1;" ::: "memory");
            } else {
                asm volatile("cp.async.wait_group 0;" ::: "memory");
            }
            __syncthreads();

            uint32_t baseB = sb + A1BYTES + buf * (3 * TERMB);
#pragma unroll
            for (int kk = 0; kk < 2; kk++) {
                uint32_t aF[3][4][4];
                uint32_t bF[3][4][2];
#pragma unroll
                for (int t = 0; t < 3; t++) {
#pragma unroll
                    for (int mi = 0; mi < 4; mi++) {
                        uint32_t addr = sb + (t * 4 + kt) * TERMB
                            + (wm + mi * 16 + (lane & 15)) * 80
                            + kk * 32 + (lane >> 4) * 16;
                        ldsm_x4(aF[t][mi], addr);
                    }
#pragma unroll
                    for (int nt = 0; nt < 2; nt++) {
                        int row = wn + nt * 16 + ((lane >> 4) & 1) * 8 + (lane & 7);
                        uint32_t addr = baseB + t * TERMB
                            + row * 80 + kk * 32 + ((lane >> 3) & 1) * 16;
                        uint32_t r[4];
                        ldsm_x4(r, addr);
                        bF[t][nt * 2][0]     = r[0]; bF[t][nt * 2][1]     = r[1];
                        bF[t][nt * 2 + 1][0] = r[2]; bF[t][nt * 2 + 1][1] = r[3];
                    }
                }
#pragma unroll
                for (int p = 0; p < 6; p++) {
#pragma unroll
                    for (int mi = 0; mi < 4; mi++)
#pragma unroll
                        for (int ni = 0; ni < 4; ni++)
                            mma16816(acc[mi][ni], aF[PA[p]][mi], bF[PB[p]][ni]);
                }
            }
            __syncthreads();
            buf ^= 1;
        }

        int n0 = n * 128;
#pragma unroll
        for (int mi = 0; mi < 4; mi++) {
#pragma unroll
            for (int ni = 0; ni < 4; ni++) {
                int r0 = m0 + wm + mi * 16 + (lane >> 2);
                int r1 = r0 + 8;
                int c  = n0 + wn + ni * 8 + (lane & 3) * 2;
                float bz0 = __ldg(bias + c)     + t_feat * __ldg(tw + c);
                float bz1 = __ldg(bias + c + 1) + t_feat * __ldg(tw + c + 1);
                float v00 = gelu_f(acc[mi][ni][0] + bz0);
                float v01 = gelu_f(acc[mi][ni][1] + bz1);
                float v10 = gelu_f(acc[mi][ni][2] + bz0);
                float v11 = gelu_f(acc[mi][ni][3] + bz1);
                *(float2*)(out + (size_t)r0 * H_ + c) = make_float2(v00, v01);
                *(float2*)(out + (size_t)r1 * H_ + c) = make_float2(v10, v11);
            }
        }
    }
}

// ================= GEMM2: K=512 streaming (proven config) ===============
static constexpr int ABYTES = 2 * 3 * TERMB;
static constexpr int SMEMB2 = 2 * ABYTES;

__global__ __launch_bounds__(256, 1)
void gemm2_k(const float* __restrict__ A,
             const __nv_bfloat16* __restrict__ Bt0, const __nv_bfloat16* __restrict__ Bt1,
             const __nv_bfloat16* __restrict__ Bt2,
             const float* __restrict__ bias, float* __restrict__ out)
{
    extern __shared__ char smem[];
    const uint32_t sb = smem_u32(smem);
    const int tid = threadIdx.x, lane = tid & 31, wid = tid >> 5;
    const int m0 = blockIdx.y * 128, n0 = blockIdx.x * 128;
    const int wm = (wid >> 2) * 64, wn = (wid & 3) * 32;
    const int KTOT = H_;

    float acc[4][4][4];
#pragma unroll
    for (int a = 0; a < 4; a++)
#pragma unroll
        for (int b = 0; b < 4; b++)
#pragma unroll
            for (int c = 0; c < 4; c++) acc[a][b][c] = 0.0f;

    float4 aR[4];
    auto ldgA = [&](int kt) {
#pragma unroll
        for (int i = 0; i < 4; i++) {
            int f = tid + i * 256;
            aR[i] = *(const float4*)(A + (size_t)(m0 + (f >> 3)) * KTOT + kt * 32 + (f & 7) * 4);
        }
    };
    auto stsA = [&](int buf) {
        uint32_t base = sb + buf * (3 * TERMB);
#pragma unroll
        for (int i = 0; i < 4; i++) {
            int f = tid + i * 256;
            float x[4] = { aR[i].x, aR[i].y, aR[i].z, aR[i].w };
            unsigned short s0[4], s1[4], s2[4];
#pragma unroll
            for (int j = 0; j < 4; j++) split3(x[j], s0[j], s1[j], s2[j]);
            uint32_t addr = base + (f >> 3) * 80 + (f & 7) * 8;
            STS64v(addr,             (uint32_t)s0[0] | ((uint32_t)s0[1] << 16),
                                     (uint32_t)s0[2] | ((uint32_t)s0[3] << 16));
            STS64v(addr + TERMB,     (uint32_t)s1[0] | ((uint32_t)s1[1] << 16),
                                     (uint32_t)s1[2] | ((uint32_t)s1[3] << 16));
            STS64v(addr + 2 * TERMB, (uint32_t)s2[0] | ((uint32_t)s2[1] << 16),
                                     (uint32_t)s2[2] | ((uint32_t)s2[3] << 16));
        }
    };
    auto cpB = [&](int kt, int buf) {
        uint32_t base = sb + ABYTES + buf * (3 * TERMB);
#pragma unroll
        for (int i = 0; i < 6; i++) {
            int rem = (i & 1) * 256 + tid;
            int row = rem >> 2, ch = rem & 3;
            const __nv_bfloat16* src = (i < 2) ? Bt0 : ((i < 4) ? Bt1 : Bt2);
            cp_async16(base + (i >> 1) * TERMB + row * 80 + ch * 16,
                       src + (size_t)(n0 + row) * KTOT + kt * 32 + ch * 8);
        }
        asm volatile("cp.async.commit_group;" ::: "memory");
    };

    const int NKT = KTOT / 32;
    ldgA(0);
    cpB(0, 0);
    int buf = 0;

    const int PA[6] = { 0, 0, 1, 1, 0, 2 };
    const int PB[6] = { 0, 1, 0, 1, 2, 0 };

#pragma unroll 1
    for (int kt = 0; kt < NKT; kt++) {
        stsA(buf);
        if (kt + 1 < NKT) {
            cpB(kt + 1, buf ^ 1);
            ldgA(kt + 1);
            asm volatile("cp.async.wait_group 1;" ::: "memory");
        } else {
            asm volatile("cp.async.wait_group 0;" ::: "memory");
        }
        __syncthreads();

        uint32_t baseA = sb + buf * (3 * TERMB);
        uint32_t baseB = sb + ABYTES + buf * (3 * TERMB);
#pragma unroll
        for (int kk = 0; kk < 2; kk++) {
            uint32_t aF[3][4][4];
            uint32_t bF[3][4][2];
#pragma unroll
            for (int t = 0; t < 3; t++) {
#pragma unroll
                for (int mi = 0; mi < 4; mi++) {
                    uint32_t addr = baseA + t * TERMB
                        + (wm + mi * 16 + (lane & 15)) * 80
                        + kk * 32 + (lane >> 4) * 16;
                    ldsm_x4(aF[t][mi], addr);
                }
#pragma unroll
                for (int nt = 0; nt < 2; nt++) {
                    int row = wn + nt * 16 + ((lane >> 4) & 1) * 8 + (lane & 7);
                    uint32_t addr = baseB + t * TERMB
                        + row * 80 + kk * 32 + ((lane >> 3) & 1) * 16;
                    uint32_t r[4];
                    ldsm_x4(r, addr);
                    bF[t][nt * 2][0]     = r[0]; bF[t][nt * 2][1]     = r[1];
                    bF[t][nt * 2 + 1][0] = r[2]; bF[t][nt * 2 + 1][1] = r[3];
                }
            }
#pragma unroll
            for (int p = 0; p < 6; p++) {
#pragma unroll
                for (int mi = 0; mi < 4; mi++)
#pragma unroll
                    for (int ni = 0; ni < 4; ni++)
                        mma16816(acc[mi][ni], aF[PA[p]][mi], bF[PB[p]][ni]);
            }
        }
        __syncthreads();
        buf ^= 1;
    }

#pragma unroll
    for (int mi = 0; mi < 4; mi++) {
#pragma unroll
        for (int ni = 0; ni < 4; ni++) {
            int r0 = m0 + wm + mi * 16 + (lane >> 2);
            int r1 = r0 + 8;
            int c  = n0 + wn + ni * 8 + (lane & 3) * 2;
            float bz0 = __ldg(bias + c);
            float bz1 = __ldg(bias + c + 1);
            *(float2*)(out + (size_t)r0 * C_ + c) = make_float2(acc[mi][ni][0] + bz0, acc[mi][ni][1] + bz1);
            *(float2*)(out + (size_t)r1 * C_ + c) = make_float2(acc[mi][ni][2] + bz0, acc[mi][ni][3] + bz1);
        }
    }
}

// ---------------- fused: entropy + obs_err partials + pooling + hist16 ---
__global__ __launch_bounds__(1024)
void fstats_k(const float* __restrict__ z, const float* __restrict__ y,
              const float* __restrict__ msk)
{
    int blk = blockIdx.x;
    int tid = threadIdx.x;
    __shared__ float ent_s[1024];
    __shared__ float rs[1024], rq[1024];

    int p = blk * 1024 + tid;
    float sa = 0.0f;
#pragma unroll
    for (int b = 0; b < B_; b++) sa += fabsf(g_eps[(size_t)b * LC_ + p]);
    float e = sa * (1.0f / B_);
    g_ent[p] = e;
    ent_s[tid] = e;
    atomicAdd(&g_hist[__float_as_uint(e) >> 16], 1u);

    float ps = 0.0f, pq = 0.0f;
#pragma unroll
    for (int b = 0; b < B_; b++) {
        size_t o = (size_t)b * LC_ + p;
        float t = (z[o] - y[o]) * msk[o];
        ps += t; pq += t * t;
    }
    rs[tid] = ps; rq[tid] = pq;
    __syncthreads();
    for (int st = 512; st > 0; st >>= 1) {
        if (tid < st) { rs[tid] += rs[tid + st]; rq[tid] += rq[tid + st]; }
        __syncthreads();
    }
    if (tid == 0) { g_part[blk] = rs[0]; g_part[512 + blk] = rq[0]; }

    if (tid < 256) {   // w=2: 4x64
        int pr = tid >> 6, pc = tid & 63;
        float s = 0.0f;
        for (int a = 0; a < 2; a++)
            for (int b = 0; b < 2; b++)
                s += ent_s[(pr * 2 + a) * 128 + pc * 2 + b];
        float v = s * 0.25f;
        g_p1[(blk * 4 + pr) * 64 + pc] = v;
        atomicAdd(&g_hist[65536 + (__float_as_uint(v) >> 16)], 1u);
    }
    if (tid < 64) {  // w=4: 2x32
        int pr = tid >> 5, pc = tid & 31;
        float s = 0.0f;
        for (int a = 0; a < 4; a++)
            for (int b = 0; b < 4; b++)
                s += ent_s[(pr * 4 + a) * 128 + pc * 4 + b];
        float v = s * (1.0f / 16.0f);
        g_p2[(blk * 2 + pr) * 32 + pc] = v;
        atomicAdd(&g_hist[2 * 65536 + (__float_as_uint(v) >> 16)], 1u);
    }
    if (tid < 16) {  // w=8: 1x16
        float s = 0.0f;
        for (int a = 0; a < 8; a++)
            for (int b = 0; b < 8; b++)
                s += ent_s[a * 128 + tid * 8 + b];
        float v = s * (1.0f / 64.0f);
        g_p3[blk * 16 + tid] = v;
        atomicAdd(&g_hist[3 * 65536 + (__float_as_uint(v) >> 16)], 1u);
    }
}

// ---------------- grid-parallel two-level radix select ----------------
__device__ __forceinline__ const float* sel_elem(int g, int& s, int& i) {
    if (g < 131072)      { s = 0; i = g;          return g_ent; }
    else if (g < 163840) { s = 1; i = g - 131072; return g_p1;  }
    else if (g < 172032) { s = 2; i = g - 163840; return g_p2;  }
    else                 { s = 3; i = g - 172032; return g_p3;  }
}

__global__ __launch_bounds__(256)
void hist2_k()
{
    int g = blockIdx.x * 256 + threadIdx.x;
    int s, i;
    const float* d = sel_elem(g, s, i);
    unsigned u = __float_as_uint(d[i]);
    if ((u >> 16) == g_pref[s])
        atomicAdd(&g_hist[s * 65536 + (u & 0xFFFFu)], 1u);
}

template<int LEVEL>
__global__ __launch_bounds__(1024)
void scan_k()
{
    int s = blockIdx.x;
    int t = threadIdx.x;

    if (LEVEL == 1 && s == 4) {   // variance finalize (128 block partials)
        __shared__ float rs[128], rq[128];
        if (t < 128) { rs[t] = g_part[t]; rq[t] = g_part[512 + t]; }
        __syncthreads();
        for (int st = 64; st > 0; st >>= 1) {
            if (t < st) { rs[t] += rs[t + st]; rq[t] += rq[t + st]; }
            __syncthreads();
        }
        if (t == 0) { g_stats[0] = rs[0]; g_stats[1] = rq[0]; }
        return;
    }

    unsigned* h = g_hist + s * 65536;
    unsigned K = (LEVEL == 0) ? (unsigned)c_K[s] : g_krem[s];

    unsigned p = 0;
#pragma unroll 8
    for (int j = 0; j < 64; j++) p += h[t * 64 + j];

    __shared__ unsigned ssA[1024], ssB[1024];
    ssA[t] = p;
    __syncthreads();
    unsigned* src = ssA; unsigned* dst = ssB;
#pragma unroll
    for (int off = 1; off < 1024; off <<= 1) {
        unsigned v = src[t] + ((t + off < 1024) ? src[t + off] : 0u);
        __syncthreads();
        dst[t] = v;
        __syncthreads();
        unsigned* tmp = src; src = dst; dst = tmp;
    }
    unsigned incl = src[t];
    unsigned above = incl - p;

    if (incl >= K && above < K) {
        unsigned cum = above;
        for (int j = 63; j >= 0; j--) {
            unsigned c = h[t * 64 + j];
            if (cum + c >= K) {
                unsigned bin = (unsigned)(t * 64 + j);
                if (LEVEL == 0) { g_pref[s] = bin; g_krem[s] = K - cum; }
                else            g_T[s] = __uint_as_float((g_pref[s] << 16) | bin);
                break;
            }
            cum += c;
        }
    }
    __syncthreads();
#pragma unroll 8
    for (int j = 0; j < 64; j++) h[t * 64 + j] = 0u;
}

// ---------------- final update (vectorized x4) ----------------
__global__ __launch_bounds__(256)
void update_k(const float* __restrict__ z, const float* __restrict__ y,
              const float* __restrict__ msk, float* __restrict__ out,
              float base_a, float base_b, float h_lam)
{
    int q = blockIdx.x * 256 + threadIdx.x;   // q < LC_/4
    int i = q * 4;                            // 4 consecutive channels, same row
    int l = i / C_, c0 = i % C_;

    float t0 = g_T[0], t1 = g_T[1], t2 = g_T[2], t3 = g_T[3];
    float4 e0 = *(const float4*)(g_ent + i);
    float pv1a = g_p1[(l >> 1) * (C_ / 2) + ((c0    ) >> 1)];
    float pv1b = g_p1[(l >> 1) * (C_ / 2) + ((c0 + 2) >> 1)];
    float pv2  = g_p2[(l >> 2) * (C_ / 4) + (c0 >> 2)];
    float pv3  = g_p3[(l >> 3) * (C_ / 8) + (c0 >> 3)];

    const float invN = 1.0f / (float)(B_ * LC_);
    float mean = g_stats[0] * invN;
    float var  = g_stats[1] * invN - mean * mean;
    float inv_d = 1.0f / (var + 1e-8f);

    float ga[4], bb[4];  int sel[4];
    float ev[4] = { e0.x, e0.y, e0.z, e0.w };
    float p1v[4] = { pv1a, pv1a, pv1b, pv1b };
#pragma unroll
    for (int j = 0; j < 4; j++) {
        int sf = -1; float ent = 0.0f;
        if (ev[j] >= t0)      { sf = 0; ent = ev[j]; }
        else if (p1v[j] >= t1){ sf = 1; ent = p1v[j]; }
        else if (pv2 >= t2)   { sf = 2; ent = pv2; }
        else if (pv3 >= t3)   { sf = 3; ent = pv3; }
        sel[j] = sf;
        float om1 = (ent > 0.1f ? 1.0f : 0.0f) + (ent > 0.5f ? 1.0f : 0.0f);
        float corr = 1.0f + om1 * 0.5f * h_lam
                   + om1 * (om1 - 1.0f) * (1.0f / 6.0f) * h_lam * h_lam;
        ga[j] = 2.0f * ent / (ent + 1.0f);
        bb[j] = base_b * corr;
    }

#pragma unroll
    for (int b = 0; b < B_; b++) {
        size_t o = (size_t)b * LC_ + i;
        float4 zv = *(const float4*)(z + o);
        float4 yv = *(const float4*)(y + o);
        float4 mv = *(const float4*)(msk + o);
        float4 epv = *(const float4*)(g_eps + o);
        float zz[4] = { zv.x, zv.y, zv.z, zv.w };
        float yy[4] = { yv.x, yv.y, yv.z, yv.w };
        float mm[4] = { mv.x, mv.y, mv.z, mv.w };
        float ee[4] = { epv.x, epv.y, epv.z, epv.w };
        float ov[4];
#pragma unroll
        for (int j = 0; j < 4; j++) {
            if (sel[j] < 0) ov[j] = zz[j];
            else {
                float gd = -(zz[j] - yy[j]) * mm[j] * inv_d;
                ov[j] = base_a * zz[j] - bb[j] * ee[j] + ga[j] * gd;
            }
        }
        *(float4*)(out + o) = make_float4(ov[0], ov[1], ov[2], ov[3]);
    }
}

// ---------------- host driver ----------------
extern "C" void kernel_launch(void* const* d_in, const int* in_sizes, int n_in,
                              void* d_out, int out_size)
{
    const float* y   = (const float*)d_in[0];
    const float* msk = (const float*)d_in[1];
    const float* z0  = (const float*)d_in[2];
    const float* W1  = (const float*)d_in[3];
    const float* b1  = (const float*)d_in[4];
    const float* W2  = (const float*)d_in[5];
    const float* b2  = (const float*)d_in[6];
    const float* tw  = (const float*)d_in[7];

    static float ac[1000];
    {
        float run = 1.0f;
        for (int i = 0; i < 1000; i++) {
            float beta = 1e-4f + (0.02f - 1e-4f) * ((float)i / 999.0f);
            run *= (1.0f - beta);
            ac[i] = run;
        }
    }
    auto alpha_at = [&](int i) { return sqrtf(ac[i]); };
    auto sigma_at = [&](int i) { return sqrtf(1.0f - ac[i]); };
    auto lam_at   = [&](int i) { return logf(alpha_at(i)) - logf(sigma_at(i)); };

    float *p_h, *p_eps, *p_za, *p_zb;
    cudaGetSymbolAddress((void**)&p_h,   g_h);
    cudaGetSymbolAddress((void**)&p_eps, g_eps);
    cudaGetSymbolAddress((void**)&p_za,  g_za);
    cudaGetSymbolAddress((void**)&p_zb,  g_zb);
    __nv_bfloat16 *b1t0, *b1t1, *b1t2, *b2t0, *b2t1, *b2t2;
    cudaGetSymbolAddress((void**)&b1t0, g_b1t0);
    cudaGetSymbolAddress((void**)&b1t1, g_b1t1);
    cudaGetSymbolAddress((void**)&b1t2, g_b1t2);
    cudaGetSymbolAddress((void**)&b2t0, g_b2t0);
    cudaGetSymbolAddress((void**)&b2t1, g_b2t1);
    cudaGetSymbolAddress((void**)&b2t2, g_b2t2);

    cudaFuncSetAttribute(gemm1_k, cudaFuncAttributeMaxDynamicSharedMemorySize, SMEMB1);
    cudaFuncSetAttribute(gemm2_k, cudaFuncAttributeMaxDynamicSharedMemorySize, SMEMB2);

    const float* zin[4]  = { z0,  p_za, p_zb, p_za };
    float*       zout[4] = { p_za, p_zb, p_za, (float*)d_out };

    prep_k<<<512, 256>>>(W1, W2);
    // diagnostic shims: shift ncu's profiled launch (consistently index 3
    // across R5-R12) onto gemm1_k below. ~1us total cost.
    noop_k<<<1, 32>>>();
    noop_k<<<1, 32>>>();

    const int step = 1000 / 4;
    dim3 grid2(C_ / 128, M_ / 128);   // (1, 128)

    for (int si = 0; si < 4; si++) {
        int k  = 999 - si * step;
        int kp = k - step; if (kp < 0) kp = 0;
        float t_feat = (float)k / 1000.0f;
        float h_lam  = lam_at(kp) - lam_at(k);
        float base_a = alpha_at(kp) / alpha_at(k);
        float base_b = sigma_at(kp) * (expf(h_lam) - 1.0f);

        gemm1_k<<<M_ / 128, 256, SMEMB1>>>(zin[si], b1t0, b1t1, b1t2, b1, tw, t_feat, p_h);
        gemm2_k<<<grid2, 256, SMEMB2>>>(p_h, b2t0, b2t1, b2t2, b2, p_eps);
        fstats_k<<<128, 1024>>>(zin[si], y, msk);
        scan_k<0><<<4, 1024>>>();
        hist2_k <<<680, 256>>>();
        scan_k<1><<<5, 1024>>>();
        update_k<<<LC_ / 1024, 256>>>(zin[si], y, msk, zout[si], base_a, base_b, h_lam);
    }
}